// round 1
// baseline (speedup 1.0000x reference)
#include <cuda_runtime.h>
#include <math.h>

// Problem dims (fixed by the reference)
#define B_  2
#define S_  2048
#define D_  1024
#define H_  16
#define DK_ 64
#define FF_ 4096
#define EPS_ 1e-6f

constexpr int  ROWS       = B_ * S_;                    // 4096
constexpr long OUT_ELEMS  = (long)B_ * S_ * D_;         // 4,194,304
constexpr long ATTN_ELEMS = (long)B_ * H_ * S_ * S_;    // 134,217,728

// ---------------- scratch (no allocations allowed) ----------------
__device__ float g_h  [ROWS * D_];     // ln1 out
__device__ float g_q  [ROWS * H_ * DK_];
__device__ float g_k  [ROWS * H_ * DK_];
__device__ float g_v  [ROWS * H_ * DK_];
__device__ float g_ctx[ROWS * D_];
__device__ float g_h1 [ROWS * D_];
__device__ float g_h2 [ROWS * D_];
__device__ float g_hg [ROWS * FF_];
__device__ float g_hgl[ROWS * FF_];
__device__ float g_attn[ATTN_ELEMS];   // used only if attn not part of d_out

// ---------------- block reduction ----------------
__device__ __forceinline__ float block_reduce(float v, int op /*0=sum,1=max*/) {
    __shared__ float sh[32];
    const int lane = threadIdx.x & 31;
    const int wid  = threadIdx.x >> 5;
    __syncthreads();  // protect sh across back-to-back calls
    #pragma unroll
    for (int o = 16; o > 0; o >>= 1) {
        float t = __shfl_xor_sync(0xffffffffu, v, o);
        v = op ? fmaxf(v, t) : (v + t);
    }
    if (lane == 0) sh[wid] = v;
    __syncthreads();
    if (wid == 0) {
        v = (lane < (int)(blockDim.x >> 5)) ? sh[lane] : (op ? -INFINITY : 0.0f);
        #pragma unroll
        for (int o = 16; o > 0; o >>= 1) {
            float t = __shfl_xor_sync(0xffffffffu, v, o);
            v = op ? fmaxf(v, t) : (v + t);
        }
        if (lane == 0) sh[0] = v;
    }
    __syncthreads();
    return sh[0];
}

// ---------------- layernorm: one block per row, D=1024, 256 threads ----------------
__global__ void layernorm_kernel(const float* __restrict__ x,
                                 const float* __restrict__ g,
                                 const float* __restrict__ b,
                                 float* __restrict__ y) {
    const long row = blockIdx.x;
    const float* xr = x + row * D_;
    float* yr = y + row * D_;
    const int tid = threadIdx.x;
    float v[4];
    #pragma unroll
    for (int i = 0; i < 4; i++) v[i] = xr[tid + i * 256];
    float s = v[0] + v[1] + v[2] + v[3];
    s = block_reduce(s, 0);
    const float mean = s * (1.0f / D_);
    float q = 0.0f;
    #pragma unroll
    for (int i = 0; i < 4; i++) { float d = v[i] - mean; q += d * d; }
    q = block_reduce(q, 0);
    const float rstd = rsqrtf(q * (1.0f / D_) + EPS_);
    #pragma unroll
    for (int i = 0; i < 4; i++) {
        const int c = tid + i * 256;
        yr[c] = (v[i] - mean) * rstd * g[c] + b[c];
    }
}

// ---------------- softmax over rows of length S_ (in-place) ----------------
__global__ void softmax_rows_kernel(float* __restrict__ a) {
    const long row = blockIdx.x;            // B*H*S rows
    float* r = a + row * (long)S_;
    const int tid = threadIdx.x;            // 256
    float v[8];
    float mx = -INFINITY;
    #pragma unroll
    for (int i = 0; i < 8; i++) { v[i] = r[tid + i * 256]; mx = fmaxf(mx, v[i]); }
    mx = block_reduce(mx, 1);
    float sum = 0.0f;
    #pragma unroll
    for (int i = 0; i < 8; i++) { v[i] = expf(v[i] - mx); sum += v[i]; }
    sum = block_reduce(sum, 0);
    const float inv = 1.0f / sum;
    #pragma unroll
    for (int i = 0; i < 8; i++) r[tid + i * 256] = v[i] * inv;
}

// ---------------- generic tiled SGEMM ----------------
// C[z] = alpha * A[z] @ (TB ? B[z]^T : B[z]) + bias, with epilogue.
// Batch z maps to (zb, zh) = (z / HD, z % HD); per-operand offset zb*bs?b + zh*bs?h.
// epi: 0 none, 1 += extra, 2 gelu(exact), 3 *= extra. extra uses C's indexing.
enum { EPI_NONE = 0, EPI_RES = 1, EPI_GELU = 2, EPI_MUL = 3 };

template <int BM, int BN, int BK, int TM, int TN, bool TB>
__global__ __launch_bounds__((BM / TM) * (BN / TN))
void gemm_kernel(const float* __restrict__ A, const float* __restrict__ Bm,
                 float* __restrict__ C,
                 const float* __restrict__ bias, const float* __restrict__ extra,
                 int K, int lda, int ldb, int ldc, int HD,
                 long bsAb, long bsAh, long bsBb, long bsBh, long bsCb, long bsCh,
                 float alpha, int epi) {
    constexpr int NT = (BM / TM) * (BN / TN);
    __shared__ float As[BK][BM];
    __shared__ float Bs[BK][BN];

    const int tid = threadIdx.x;
    const int tx = tid % (BN / TN);
    const int ty = tid / (BN / TN);
    const int zb = blockIdx.z / HD;
    const int zh = blockIdx.z % HD;
    const long zA = (long)zb * bsAb + (long)zh * bsAh;
    const long zB = (long)zb * bsBb + (long)zh * bsBh;
    const long zC = (long)zb * bsCb + (long)zh * bsCh;
    const int m0 = blockIdx.y * BM;
    const int n0 = blockIdx.x * BN;

    float acc[TM][TN];
    #pragma unroll
    for (int i = 0; i < TM; i++)
        #pragma unroll
        for (int j = 0; j < TN; j++) acc[i][j] = 0.0f;

    for (int k0 = 0; k0 < K; k0 += BK) {
        // load A tile (As transposed: As[k][m])
        #pragma unroll
        for (int r = 0; r < (BM * BK) / NT; r++) {
            const int i = tid + r * NT;
            const int m = i / BK, kk = i % BK;
            As[kk][m] = A[zA + (long)(m0 + m) * lda + (k0 + kk)];
        }
        // load B tile
        if (TB) {
            #pragma unroll
            for (int r = 0; r < (BN * BK) / NT; r++) {
                const int i = tid + r * NT;
                const int n = i / BK, kk = i % BK;
                Bs[kk][n] = Bm[zB + (long)(n0 + n) * ldb + (k0 + kk)];
            }
        } else {
            #pragma unroll
            for (int r = 0; r < (BN * BK) / NT; r++) {
                const int i = tid + r * NT;
                const int kk = i / BN, n = i % BN;
                Bs[kk][n] = Bm[zB + (long)(k0 + kk) * ldb + (n0 + n)];
            }
        }
        __syncthreads();

        #pragma unroll
        for (int kk = 0; kk < BK; kk++) {
            float ra[TM], rb[TN];
            #pragma unroll
            for (int i = 0; i < TM; i++) ra[i] = As[kk][ty * TM + i];
            #pragma unroll
            for (int j = 0; j < TN; j++) rb[j] = Bs[kk][tx * TN + j];
            #pragma unroll
            for (int i = 0; i < TM; i++)
                #pragma unroll
                for (int j = 0; j < TN; j++) acc[i][j] += ra[i] * rb[j];
        }
        __syncthreads();
    }

    #pragma unroll
    for (int i = 0; i < TM; i++) {
        const int m = m0 + ty * TM + i;
        #pragma unroll
        for (int j = 0; j < TN; j++) {
            const int n = n0 + tx * TN + j;
            float c = acc[i][j] * alpha;
            if (bias) c += bias[n];
            const long idx = zC + (long)m * ldc + n;
            if (epi == EPI_RES)       c += extra[idx];
            else if (epi == EPI_GELU) c = 0.5f * c * (1.0f + erff(c * 0.70710678118654752f));
            else if (epi == EPI_MUL)  c *= extra[idx];
            C[idx] = c;
        }
    }
}

// ---------------- launch ----------------
extern "C" void kernel_launch(void* const* d_in, const int* in_sizes, int n_in,
                              void* d_out, int out_size) {
    (void)in_sizes; (void)n_in;
    const float* inputs = (const float*)d_in[0];
    const float* wq = (const float*)d_in[1];  const float* bq = (const float*)d_in[2];
    const float* wk = (const float*)d_in[3];  const float* bk = (const float*)d_in[4];
    const float* wv = (const float*)d_in[5];  const float* bv = (const float*)d_in[6];
    const float* wo = (const float*)d_in[7];  const float* bo = (const float*)d_in[8];
    const float* ln1_g = (const float*)d_in[9];  const float* ln1_b = (const float*)d_in[10];
    const float* wi0 = (const float*)d_in[11]; const float* bi0 = (const float*)d_in[12];
    const float* wi1 = (const float*)d_in[13]; const float* bi1 = (const float*)d_in[14];
    const float* wff = (const float*)d_in[15]; const float* bff = (const float*)d_in[16];
    const float* ln2_g = (const float*)d_in[17]; const float* ln2_b = (const float*)d_in[18];
    float* out = (float*)d_out;

    float *h, *q, *k, *v, *ctx, *h1, *h2, *hg, *hgl, *attn_scratch;
    cudaGetSymbolAddress((void**)&h,   g_h);
    cudaGetSymbolAddress((void**)&q,   g_q);
    cudaGetSymbolAddress((void**)&k,   g_k);
    cudaGetSymbolAddress((void**)&v,   g_v);
    cudaGetSymbolAddress((void**)&ctx, g_ctx);
    cudaGetSymbolAddress((void**)&h1,  g_h1);
    cudaGetSymbolAddress((void**)&h2,  g_h2);
    cudaGetSymbolAddress((void**)&hg,  g_hg);
    cudaGetSymbolAddress((void**)&hgl, g_hgl);
    cudaGetSymbolAddress((void**)&attn_scratch, g_attn);

    // reference returns (out, attn): if d_out covers both (flattened concat),
    // write attn directly there; otherwise attn lives in scratch.
    float* attn = ((long)out_size >= OUT_ELEMS + ATTN_ELEMS) ? (out + OUT_ELEMS)
                                                             : attn_scratch;

    const int HDK = H_ * DK_;  // 1024

    // 1. h = LN1(inputs)
    layernorm_kernel<<<ROWS, 256>>>(inputs, ln1_g, ln1_b, h);

    // 2. q/k/v = h @ w{q,k,v} + b   [4096,1024] x [1024,1024]
    {
        dim3 grid(HDK / 128, ROWS / 128, 1);
        gemm_kernel<128,128,8,8,8,false><<<grid, 256>>>(h, wq, q, bq, nullptr,
            D_, D_, HDK, HDK, 1, 0,0, 0,0, 0,0, 1.0f, EPI_NONE);
        gemm_kernel<128,128,8,8,8,false><<<grid, 256>>>(h, wk, k, bk, nullptr,
            D_, D_, HDK, HDK, 1, 0,0, 0,0, 0,0, 1.0f, EPI_NONE);
        gemm_kernel<128,128,8,8,8,false><<<grid, 256>>>(h, wv, v, bv, nullptr,
            D_, D_, HDK, HDK, 1, 0,0, 0,0, 0,0, 1.0f, EPI_NONE);
    }

    // 3. scores[b,h,qi,kj] = q . k / 8   (batched A@B^T, z = b*H + h)
    {
        dim3 grid(S_ / 128, S_ / 128, B_ * H_);
        gemm_kernel<128,128,8,8,8,true><<<grid, 256>>>(q, k, attn, nullptr, nullptr,
            DK_, HDK, HDK, S_, H_,
            (long)S_ * HDK, (long)DK_,        // A = q: per-b, per-h offsets
            (long)S_ * HDK, (long)DK_,        // B = k
            (long)H_ * S_ * S_, (long)S_ * S_,// C = attn [B,H,S,S]
            0.125f, EPI_NONE);
    }

    // 4. softmax rows (in place), 65536 rows of 2048
    softmax_rows_kernel<<<B_ * H_ * S_, 256>>>(attn);

    // 5. ctx[b,s,h*64+d] = attn @ v   (batched, N=64)
    {
        dim3 grid(DK_ / 64, S_ / 128, B_ * H_);
        gemm_kernel<128,64,16,8,4,false><<<grid, 256>>>(attn, v, ctx, nullptr, nullptr,
            S_, S_, HDK, HDK, H_,
            (long)H_ * S_ * S_, (long)S_ * S_,  // A = attn
            (long)S_ * HDK, (long)DK_,          // B = v (rows = key index)
            (long)S_ * HDK, (long)DK_,          // C = ctx
            1.0f, EPI_NONE);
    }

    // 6. h1 = inputs + ctx @ wo + bo
    {
        dim3 grid(D_ / 128, ROWS / 128, 1);
        gemm_kernel<128,128,8,8,8,false><<<grid, 256>>>(ctx, wo, h1, bo, inputs,
            HDK, HDK, D_, D_, 1, 0,0, 0,0, 0,0, 1.0f, EPI_RES);
    }

    // 7. h2 = LN2(h1)
    layernorm_kernel<<<ROWS, 256>>>(h1, ln2_g, ln2_b, h2);

    // 8. hg = gelu(h2 @ wi0 + bi0)
    {
        dim3 grid(FF_ / 128, ROWS / 128, 1);
        gemm_kernel<128,128,8,8,8,false><<<grid, 256>>>(h2, wi0, hg, bi0, nullptr,
            D_, D_, FF_, FF_, 1, 0,0, 0,0, 0,0, 1.0f, EPI_GELU);
        // 9. hgl = (h2 @ wi1 + bi1) * hg
        gemm_kernel<128,128,8,8,8,false><<<grid, 256>>>(h2, wi1, hgl, bi1, hg,
            D_, D_, FF_, FF_, 1, 0,0, 0,0, 0,0, 1.0f, EPI_MUL);
    }

    // 10. out = h1 + hgl @ wff + bff
    {
        dim3 grid(D_ / 128, ROWS / 128, 1);
        gemm_kernel<128,128,8,8,8,false><<<grid, 256>>>(hgl, wff, out, bff, h1,
            FF_, FF_, D_, D_, 1, 0,0, 0,0, 0,0, 1.0f, EPI_RES);
    }
}

// round 4
// speedup vs baseline: 5.8715x; 5.8715x over previous
#include <cuda_runtime.h>
#include <math.h>

// Problem dims (fixed by the reference)
#define B_  2
#define S_  2048
#define D_  1024
#define H_  16
#define DK_ 64
#define FF_ 4096
#define EPS_ 1e-6f

constexpr int  ROWS       = B_ * S_;                    // 4096
constexpr long OUT_ELEMS  = (long)B_ * S_ * D_;         // 4,194,304
constexpr long ATTN_ELEMS = (long)B_ * H_ * S_ * S_;    // 134,217,728

// ---------------- scratch (no allocations allowed) ----------------
__device__ float g_h  [ROWS * D_];
__device__ float g_q  [ROWS * H_ * DK_];
__device__ float g_k  [ROWS * H_ * DK_];
__device__ float g_v  [ROWS * H_ * DK_];
__device__ float g_ctx[ROWS * D_];
__device__ float g_h1 [ROWS * D_];
__device__ float g_h2 [ROWS * D_];
__device__ float g_hg [ROWS * FF_];
__device__ float g_hgl[ROWS * FF_];
__device__ float g_attn[ATTN_ELEMS];

// ---------------- block reduction ----------------
__device__ __forceinline__ float block_reduce(float v, int op /*0=sum,1=max*/) {
    __shared__ float sh[32];
    const int lane = threadIdx.x & 31;
    const int wid  = threadIdx.x >> 5;
    __syncthreads();
    #pragma unroll
    for (int o = 16; o > 0; o >>= 1) {
        float t = __shfl_xor_sync(0xffffffffu, v, o);
        v = op ? fmaxf(v, t) : (v + t);
    }
    if (lane == 0) sh[wid] = v;
    __syncthreads();
    if (wid == 0) {
        v = (lane < (int)(blockDim.x >> 5)) ? sh[lane] : (op ? -INFINITY : 0.0f);
        #pragma unroll
        for (int o = 16; o > 0; o >>= 1) {
            float t = __shfl_xor_sync(0xffffffffu, v, o);
            v = op ? fmaxf(v, t) : (v + t);
        }
        if (lane == 0) sh[0] = v;
    }
    __syncthreads();
    return sh[0];
}

// ---------------- layernorm ----------------
__global__ void layernorm_kernel(const float* __restrict__ x,
                                 const float* __restrict__ g,
                                 const float* __restrict__ b,
                                 float* __restrict__ y) {
    const long row = blockIdx.x;
    const float* xr = x + row * D_;
    float* yr = y + row * D_;
    const int tid = threadIdx.x;
    float v[4];
    #pragma unroll
    for (int i = 0; i < 4; i++) v[i] = xr[tid + i * 256];
    float s = v[0] + v[1] + v[2] + v[3];
    s = block_reduce(s, 0);
    const float mean = s * (1.0f / D_);
    float q = 0.0f;
    #pragma unroll
    for (int i = 0; i < 4; i++) { float d = v[i] - mean; q += d * d; }
    q = block_reduce(q, 0);
    const float rstd = rsqrtf(q * (1.0f / D_) + EPS_);
    #pragma unroll
    for (int i = 0; i < 4; i++) {
        const int c = tid + i * 256;
        yr[c] = (v[i] - mean) * rstd * g[c] + b[c];
    }
}

// ---------------- softmax (in-place over rows of S_) ----------------
__global__ void softmax_rows_kernel(float* __restrict__ a) {
    const long row = blockIdx.x;
    float* r = a + row * (long)S_;
    const int tid = threadIdx.x;
    float v[8];
    float mx = -INFINITY;
    #pragma unroll
    for (int i = 0; i < 8; i++) { v[i] = r[tid + i * 256]; mx = fmaxf(mx, v[i]); }
    mx = block_reduce(mx, 1);
    float sum = 0.0f;
    #pragma unroll
    for (int i = 0; i < 8; i++) { v[i] = expf(v[i] - mx); sum += v[i]; }
    sum = block_reduce(sum, 0);
    const float inv = 1.0f / sum;
    #pragma unroll
    for (int i = 0; i < 8; i++) r[tid + i * 256] = v[i] * inv;
}

// ---------------- tensor-core tf32 GEMM ----------------
enum { EPI_NONE = 0, EPI_RES = 1, EPI_GELU = 2, EPI_MUL = 3 };

__device__ __forceinline__ unsigned f2tf(float f) {
    unsigned u;
    asm("cvt.rna.tf32.f32 %0, %1;" : "=r"(u) : "f"(f));
    return u;
}

__device__ __forceinline__ void mma_tf32(float* c, const unsigned* a, const unsigned* b) {
    asm volatile(
        "mma.sync.aligned.m16n8k8.row.col.f32.tf32.tf32.f32 "
        "{%0,%1,%2,%3}, {%4,%5,%6,%7}, {%8,%9}, {%0,%1,%2,%3};"
        : "+f"(c[0]), "+f"(c[1]), "+f"(c[2]), "+f"(c[3])
        : "r"(a[0]), "r"(a[1]), "r"(a[2]), "r"(a[3]), "r"(b[0]), "r"(b[1]));
}

__device__ __forceinline__ void cp_async16(void* sdst, const void* gsrc) {
    unsigned saddr = (unsigned)__cvta_generic_to_shared(sdst);
    asm volatile("cp.async.cg.shared.global [%0], [%1], 16;" :: "r"(saddr), "l"(gsrc));
}
__device__ __forceinline__ void cp_commit() { asm volatile("cp.async.commit_group;"); }
__device__ __forceinline__ void cp_wait0()  { asm volatile("cp.async.wait_group 0;"); }

// C[z][m][n] = alpha * sum_k A[m][k] * (TB ? B[n][k] : B[k][n]) (+bias, epi)
template <int BM, int BN, int BK, int WM, int WN, bool TB>
__global__ __launch_bounds__(256)
void gemm_tc_kernel(const float* __restrict__ A, const float* __restrict__ Bm,
                    float* __restrict__ C,
                    const float* __restrict__ bias, const float* __restrict__ extra,
                    int K, int lda, int ldb, int ldc, int HD,
                    long bsAb, long bsAh, long bsBb, long bsBh, long bsCb, long bsCh,
                    float alpha, int epi) {
    constexpr int THREADS = 256;
    constexpr int AS  = BK + 4;             // A smem row stride (floats)
    constexpr int BS  = BN + 8;             // B smem row stride, non-TB
    constexpr int WARPS_N = BN / WN;
    constexpr int MT = WM / 16;
    constexpr int NT = WN / 8;
    constexpr int KSTEPS = BK / 8;
    constexpr int NA4 = BM * BK / (4 * THREADS);
    constexpr int NB4 = (TB ? BN * BK : BK * BN) / (4 * THREADS);
    constexpr int ABUF = BM * AS;
    constexpr int BBUF = TB ? BN * AS : BK * BS;

    extern __shared__ float smem[];
    float* As = smem;                 // 2 * ABUF
    float* Bs = smem + 2 * ABUF;      // 2 * BBUF

    const int tid  = threadIdx.x;
    const int lane = tid & 31;
    const int g    = lane >> 2;       // groupID
    const int t    = lane & 3;        // thread-in-group
    const int w    = tid >> 5;
    const int wm0  = (w / WARPS_N) * WM;
    const int wn0  = (w % WARPS_N) * WN;

    const int zb = blockIdx.z / HD;
    const int zh = blockIdx.z % HD;
    const long zA = (long)zb * bsAb + (long)zh * bsAh;
    const long zB = (long)zb * bsBb + (long)zh * bsBh;
    const long zC = (long)zb * bsCb + (long)zh * bsCh;
    const int m0 = blockIdx.y * BM;
    const int n0 = blockIdx.x * BN;

    float acc[MT][NT][4];
    #pragma unroll
    for (int i = 0; i < MT; i++)
        #pragma unroll
        for (int j = 0; j < NT; j++)
            #pragma unroll
            for (int r = 0; r < 4; r++) acc[i][j][r] = 0.0f;

    auto load_tile = [&](int buf, int k0) {
        float* as = As + buf * ABUF;
        float* bs = Bs + buf * BBUF;
        #pragma unroll
        for (int i = 0; i < NA4; i++) {
            const int lin = (tid + i * THREADS) * 4;
            const int m = lin / BK, kk = lin % BK;
            cp_async16(&as[m * AS + kk], &A[zA + (long)(m0 + m) * lda + (k0 + kk)]);
        }
        if (TB) {
            #pragma unroll
            for (int i = 0; i < NB4; i++) {
                const int lin = (tid + i * THREADS) * 4;
                const int n = lin / BK, kk = lin % BK;
                cp_async16(&bs[n * AS + kk], &Bm[zB + (long)(n0 + n) * ldb + (k0 + kk)]);
            }
        } else {
            #pragma unroll
            for (int i = 0; i < NB4; i++) {
                const int lin = (tid + i * THREADS) * 4;
                const int kk = lin / BN, n = lin % BN;
                cp_async16(&bs[kk * BS + n], &Bm[zB + (long)(k0 + kk) * ldb + (n0 + n)]);
            }
        }
    };

    const int nk = K / BK;
    load_tile(0, 0);
    cp_commit();

    for (int kt = 0; kt < nk; kt++) {
        cp_wait0();
        __syncthreads();
        if (kt + 1 < nk) { load_tile((kt + 1) & 1, (kt + 1) * BK); cp_commit(); }

        const float* as = As + (kt & 1) * ABUF;
        const float* bs = Bs + (kt & 1) * BBUF;

        #pragma unroll
        for (int ks = 0; ks < KSTEPS; ks++) {
            const int kb = ks * 8;
            unsigned afr[MT][4];
            #pragma unroll
            for (int mt = 0; mt < MT; mt++) {
                const int rb = wm0 + mt * 16;
                afr[mt][0] = f2tf(as[(rb + g)     * AS + kb + t]);
                afr[mt][1] = f2tf(as[(rb + g + 8) * AS + kb + t]);
                afr[mt][2] = f2tf(as[(rb + g)     * AS + kb + t + 4]);
                afr[mt][3] = f2tf(as[(rb + g + 8) * AS + kb + t + 4]);
            }
            unsigned bfr[NT][2];
            #pragma unroll
            for (int nt = 0; nt < NT; nt++) {
                const int cb = wn0 + nt * 8;
                if (TB) {
                    bfr[nt][0] = f2tf(bs[(cb + g) * AS + kb + t]);
                    bfr[nt][1] = f2tf(bs[(cb + g) * AS + kb + t + 4]);
                } else {
                    bfr[nt][0] = f2tf(bs[(kb + t)     * BS + cb + g]);
                    bfr[nt][1] = f2tf(bs[(kb + t + 4) * BS + cb + g]);
                }
            }
            #pragma unroll
            for (int mt = 0; mt < MT; mt++)
                #pragma unroll
                for (int nt = 0; nt < NT; nt++)
                    mma_tf32(acc[mt][nt], afr[mt], bfr[nt]);
        }
        __syncthreads();
    }

    // epilogue
    #pragma unroll
    for (int mt = 0; mt < MT; mt++) {
        #pragma unroll
        for (int nt = 0; nt < NT; nt++) {
            const int col = n0 + wn0 + nt * 8 + 2 * t;
            const float bsum  = bias ? bias[col] : 0.0f;
            const float bsum1 = bias ? bias[col + 1] : 0.0f;
            #pragma unroll
            for (int half = 0; half < 2; half++) {
                const int row = m0 + wm0 + mt * 16 + g + half * 8;
                float c0 = acc[mt][nt][half * 2 + 0] * alpha + bsum;
                float c1 = acc[mt][nt][half * 2 + 1] * alpha + bsum1;
                const long idx = zC + (long)row * ldc + col;
                if (epi == EPI_RES) {
                    const float2 e = *(const float2*)&extra[idx];
                    c0 += e.x; c1 += e.y;
                } else if (epi == EPI_GELU) {
                    c0 = 0.5f * c0 * (1.0f + erff(c0 * 0.70710678118654752f));
                    c1 = 0.5f * c1 * (1.0f + erff(c1 * 0.70710678118654752f));
                } else if (epi == EPI_MUL) {
                    const float2 e = *(const float2*)&extra[idx];
                    c0 *= e.x; c1 *= e.y;
                }
                float2 o; o.x = c0; o.y = c1;
                *(float2*)&C[idx] = o;
            }
        }
    }
}

// host-side smem sizing (mirrors device)
static constexpr int smem_bytes(int BM, int BN, int BK, bool TB) {
    return (2 * BM * (BK + 4) + 2 * (TB ? BN * (BK + 4) : BK * (BN + 8))) * 4;
}

// ---------------- launch ----------------
extern "C" void kernel_launch(void* const* d_in, const int* in_sizes, int n_in,
                              void* d_out, int out_size) {
    (void)in_sizes; (void)n_in;
    const float* inputs = (const float*)d_in[0];
    const float* wq = (const float*)d_in[1];  const float* bq = (const float*)d_in[2];
    const float* wk = (const float*)d_in[3];  const float* bk = (const float*)d_in[4];
    const float* wv = (const float*)d_in[5];  const float* bv = (const float*)d_in[6];
    const float* wo = (const float*)d_in[7];  const float* bo = (const float*)d_in[8];
    const float* ln1_g = (const float*)d_in[9];  const float* ln1_b = (const float*)d_in[10];
    const float* wi0 = (const float*)d_in[11]; const float* bi0 = (const float*)d_in[12];
    const float* wi1 = (const float*)d_in[13]; const float* bi1 = (const float*)d_in[14];
    const float* wff = (const float*)d_in[15]; const float* bff = (const float*)d_in[16];
    const float* ln2_g = (const float*)d_in[17]; const float* ln2_b = (const float*)d_in[18];
    float* out = (float*)d_out;

    float *h, *q, *k, *v, *ctx, *h1, *h2, *hg, *hgl, *attn_scratch;
    cudaGetSymbolAddress((void**)&h,   g_h);
    cudaGetSymbolAddress((void**)&q,   g_q);
    cudaGetSymbolAddress((void**)&k,   g_k);
    cudaGetSymbolAddress((void**)&v,   g_v);
    cudaGetSymbolAddress((void**)&ctx, g_ctx);
    cudaGetSymbolAddress((void**)&h1,  g_h1);
    cudaGetSymbolAddress((void**)&h2,  g_h2);
    cudaGetSymbolAddress((void**)&hg,  g_hg);
    cudaGetSymbolAddress((void**)&hgl, g_hgl);
    cudaGetSymbolAddress((void**)&attn_scratch, g_attn);

    float* attn = ((long)out_size >= OUT_ELEMS + ATTN_ELEMS) ? (out + OUT_ELEMS)
                                                             : attn_scratch;
    const int HDK = H_ * DK_;  // 1024

    // kernel variants
    auto kMain   = gemm_tc_kernel<128,128,32,32,64,false>;  // square / FFN GEMMs
    auto kScores = gemm_tc_kernel<128,128,32,32,64,true>;   // q @ k^T
    auto kCtx    = gemm_tc_kernel<128, 64,32,32,32,false>;  // attn @ v
    const int smMain   = smem_bytes(128,128,32,false);
    const int smScores = smem_bytes(128,128,32,true);
    const int smCtx    = smem_bytes(128, 64,32,false);
    cudaFuncSetAttribute(kMain,   cudaFuncAttributeMaxDynamicSharedMemorySize, smMain);
    cudaFuncSetAttribute(kScores, cudaFuncAttributeMaxDynamicSharedMemorySize, smScores);
    cudaFuncSetAttribute(kCtx,    cudaFuncAttributeMaxDynamicSharedMemorySize, smCtx);

    // 1. h = LN1(inputs)
    layernorm_kernel<<<ROWS, 256>>>(inputs, ln1_g, ln1_b, h);

    // 2. q/k/v = h @ w{q,k,v} + b
    {
        dim3 grid(HDK / 128, ROWS / 128, 1);
        kMain<<<grid, 256, smMain>>>(h, wq, q, bq, nullptr,
            D_, D_, HDK, HDK, 1, 0,0, 0,0, 0,0, 1.0f, EPI_NONE);
        kMain<<<grid, 256, smMain>>>(h, wk, k, bk, nullptr,
            D_, D_, HDK, HDK, 1, 0,0, 0,0, 0,0, 1.0f, EPI_NONE);
        kMain<<<grid, 256, smMain>>>(h, wv, v, bv, nullptr,
            D_, D_, HDK, HDK, 1, 0,0, 0,0, 0,0, 1.0f, EPI_NONE);
    }

    // 3. scores = q @ k^T / 8   (batched over B*H)
    {
        dim3 grid(S_ / 128, S_ / 128, B_ * H_);
        kScores<<<grid, 256, smScores>>>(q, k, attn, nullptr, nullptr,
            DK_, HDK, HDK, S_, H_,
            (long)S_ * HDK, (long)DK_,
            (long)S_ * HDK, (long)DK_,
            (long)H_ * S_ * S_, (long)S_ * S_,
            0.125f, EPI_NONE);
    }

    // 4. softmax rows
    softmax_rows_kernel<<<B_ * H_ * S_, 256>>>(attn);

    // 5. ctx = attn @ v   (batched, N=64 per head)
    {
        dim3 grid(1, S_ / 128, B_ * H_);
        kCtx<<<grid, 256, smCtx>>>(attn, v, ctx, nullptr, nullptr,
            S_, S_, HDK, HDK, H_,
            (long)H_ * S_ * S_, (long)S_ * S_,
            (long)S_ * HDK, (long)DK_,
            (long)S_ * HDK, (long)DK_,
            1.0f, EPI_NONE);
    }

    // 6. h1 = inputs + ctx @ wo + bo
    {
        dim3 grid(D_ / 128, ROWS / 128, 1);
        kMain<<<grid, 256, smMain>>>(ctx, wo, h1, bo, inputs,
            HDK, HDK, D_, D_, 1, 0,0, 0,0, 0,0, 1.0f, EPI_RES);
    }

    // 7. h2 = LN2(h1)
    layernorm_kernel<<<ROWS, 256>>>(h1, ln2_g, ln2_b, h2);

    // 8/9. GeGLU
    {
        dim3 grid(FF_ / 128, ROWS / 128, 1);
        kMain<<<grid, 256, smMain>>>(h2, wi0, hg, bi0, nullptr,
            D_, D_, FF_, FF_, 1, 0,0, 0,0, 0,0, 1.0f, EPI_GELU);
        kMain<<<grid, 256, smMain>>>(h2, wi1, hgl, bi1, hg,
            D_, D_, FF_, FF_, 1, 0,0, 0,0, 0,0, 1.0f, EPI_MUL);
    }

    // 10. out = h1 + hgl @ wff + bff
    {
        dim3 grid(D_ / 128, ROWS / 128, 1);
        kMain<<<grid, 256, smMain>>>(hgl, wff, out, bff, h1,
            FF_, FF_, D_, D_, 1, 0,0, 0,0, 0,0, 1.0f, EPI_RES);
    }
}